// round 13
// baseline (speedup 1.0000x reference)
#include <cuda_runtime.h>
#include <cuda_fp16.h>
#include <cstdint>
#include <cstdio>

// Problem constants
#define Bsz 8
#define Tn  1024
#define Vn  8192
#define Dn  1024
#define Hn  16
#define Ln  6
#define HDn 64
#define BT  (Bsz*Tn)      // 8192 rows
#define D3  (3*Dn)        // 3072

// ---------------------------------------------------------------------------
// Scratch
// ---------------------------------------------------------------------------
__device__ float  g_x[(size_t)BT * Dn];
__device__ __half g_h[(size_t)BT * Dn];              // LN output (fp16)
__device__ float  g_qkv[(size_t)BT * D3];
__device__ float  g_logits_scratch[(size_t)BT * Vn];
__device__ __half g_wattn_h[(size_t)Ln * D3 * Dn];   // fp16 W_attn
__device__ __half g_wout_h[(size_t)Vn * Dn];         // fp16 W_out
__device__ float  g_wembT[(size_t)Vn * Dn];          // W_emb transposed [V,D]
__device__ int    g_tok[BT];
__device__ float  g_nll[BT];

// ---------------------------------------------------------------------------
// helpers
// ---------------------------------------------------------------------------
__device__ __forceinline__ uint32_t smem_u32(const void* p) {
    uint32_t a;
    asm("{ .reg .u64 t; cvta.to.shared.u64 t, %1; cvt.u32.u64 %0, t; }"
        : "=r"(a) : "l"(p));
    return a;
}
__device__ __forceinline__ void cp_async16(uint32_t dst, const void* src) {
    asm volatile("cp.async.cg.shared.global [%0], [%1], 16;" :: "r"(dst), "l"(src));
}
__device__ __forceinline__ void cp_commit() {
    asm volatile("cp.async.commit_group;" ::: "memory");
}
template <int N> __device__ __forceinline__ void cp_wait() {
    asm volatile("cp.async.wait_group %0;" :: "n"(N) : "memory");
}
__device__ __forceinline__ void ldm4(uint32_t* r, uint32_t addr) {
    asm volatile("ldmatrix.sync.aligned.m8n8.x4.shared.b16 {%0,%1,%2,%3}, [%4];"
                 : "=r"(r[0]), "=r"(r[1]), "=r"(r[2]), "=r"(r[3]) : "r"(addr));
}
__device__ __forceinline__ void ldm4t(uint32_t* r, uint32_t addr) {
    asm volatile("ldmatrix.sync.aligned.m8n8.x4.trans.shared.b16 {%0,%1,%2,%3}, [%4];"
                 : "=r"(r[0]), "=r"(r[1]), "=r"(r[2]), "=r"(r[3]) : "r"(addr));
}
__device__ __forceinline__ void mma_f16(float* c, const uint32_t* a,
                                        uint32_t b0, uint32_t b1) {
    asm volatile(
        "mma.sync.aligned.m16n8k16.row.col.f32.f16.f16.f32 "
        "{%0,%1,%2,%3}, {%4,%5,%6,%7}, {%8,%9}, {%0,%1,%2,%3};"
        : "+f"(c[0]), "+f"(c[1]), "+f"(c[2]), "+f"(c[3])
        : "r"(a[0]), "r"(a[1]), "r"(a[2]), "r"(a[3]), "r"(b0), "r"(b1));
}
__device__ __forceinline__ void splith2(float x, float y, __half2& hi, __half2& lo) {
    hi = __floats2half2_rn(x, y);
    float2 b = __half22float2(hi);
    lo = __floats2half2_rn(x - b.x, y - b.y);
}

// ---------------------------------------------------------------------------
// 0a. Convert fp32 weights to fp16 once per launch
// ---------------------------------------------------------------------------
__global__ void __launch_bounds__(256) f2h_kernel(const float2* __restrict__ in,
                                                  __half2* __restrict__ out, int n2) {
    for (int i = blockIdx.x * 256 + threadIdx.x; i < n2; i += gridDim.x * 256) {
        float2 v = in[i];
        out[i] = __floats2half2_rn(v.x, v.y);
    }
}

// ---------------------------------------------------------------------------
// 0b. Transpose W_emb [D,V] -> [V,D] (tiled, conflict-free)
// ---------------------------------------------------------------------------
__global__ void __launch_bounds__(256) wembT_kernel(const float* __restrict__ in,
                                                    float* __restrict__ out) {
    __shared__ float t[32][33];
    const int bv = blockIdx.x * 32, bd = blockIdx.y * 32;
    const int tx = threadIdx.x & 31, ty = threadIdx.x >> 5;   // 32x8
    #pragma unroll
    for (int i = 0; i < 32; i += 8)
        t[ty + i][tx] = in[(size_t)(bd + ty + i) * Vn + bv + tx];
    __syncthreads();
    #pragma unroll
    for (int i = 0; i < 32; i += 8)
        out[(size_t)(bv + ty + i) * Dn + bd + tx] = t[tx][ty + i];
}

// ---------------------------------------------------------------------------
// 1. Token ids from one-hot (float4 scan)
// ---------------------------------------------------------------------------
__global__ void __launch_bounds__(256) tok_kernel(const float* __restrict__ idx,
                                                  int* __restrict__ tok) {
    const int row = blockIdx.x;
    const float4* r = (const float4*)(idx + (size_t)row * Vn);
    for (int v = threadIdx.x; v < Vn / 4; v += 256) {
        float4 q = r[v];
        if (q.x > 0.5f) tok[row] = 4 * v;
        if (q.y > 0.5f) tok[row] = 4 * v + 1;
        if (q.z > 0.5f) tok[row] = 4 * v + 2;
        if (q.w > 0.5f) tok[row] = 4 * v + 3;
    }
}

// ---------------------------------------------------------------------------
// 2. Embedding gather (coalesced via transposed table)
// ---------------------------------------------------------------------------
__global__ void __launch_bounds__(256) embed_kernel(const float* __restrict__ WT,
                                                    const int* __restrict__ tok,
                                                    float* __restrict__ x) {
    const int row = blockIdx.x;
    const int t = tok[row];
    const float4* src = (const float4*)(WT + (size_t)t * Dn);
    float4* dst = (float4*)(x + (size_t)row * Dn);
    dst[threadIdx.x] = src[threadIdx.x];     // 256 threads x float4 = 1024 floats
}

// ---------------------------------------------------------------------------
// 3. LayerNorm -> fp16 output
// ---------------------------------------------------------------------------
__global__ void __launch_bounds__(256) ln_kernel(const float* __restrict__ in,
                                                 __half* __restrict__ out) {
    const int row = blockIdx.x;
    const float* r = in + (size_t)row * Dn;
    float s = 0.f, ss = 0.f;
    for (int d = threadIdx.x; d < Dn; d += 256) {
        float v = r[d];
        s += v; ss += v * v;
    }
    #pragma unroll
    for (int o = 16; o > 0; o >>= 1) {
        s  += __shfl_xor_sync(0xffffffffu, s,  o);
        ss += __shfl_xor_sync(0xffffffffu, ss, o);
    }
    __shared__ float sb[8], qb[8];
    const int w = threadIdx.x >> 5, lane = threadIdx.x & 31;
    if (lane == 0) { sb[w] = s; qb[w] = ss; }
    __syncthreads();
    float ts = 0.f, tq = 0.f;
    #pragma unroll
    for (int i = 0; i < 8; i++) { ts += sb[i]; tq += qb[i]; }
    const float mu   = ts * (1.0f / Dn);
    const float var  = tq * (1.0f / Dn) - mu * mu;
    const float rstd = rsqrtf(var + 1e-5f);
    __half* o2 = out + (size_t)row * Dn;
    for (int d = threadIdx.x; d < Dn; d += 256)
        o2[d] = __float2half_rn((r[d] - mu) * rstd);
}

// ---------------------------------------------------------------------------
// 4. fp16 HMMA GEMM (round-10 config: CTA 128x128, 4 warps, warp tile 64x64,
//    BK=64, 3-stage cp.async, 2 CTAs/SM). C[M,N] = A[M,K]*B[N,K]^T; K=1024.
// ---------------------------------------------------------------------------
#define GS 3
#define G_HST 72
#define G_TILEH (128 * G_HST)
#define G_STAGEH (2 * G_TILEH)
#define G_SMEM (GS * G_STAGEH * 2)      // 110592 bytes
#define G_NCH (Dn / 64)                 // 16

__global__ void __launch_bounds__(128, 2) gemm_f16_kernel(
    const __half* __restrict__ A, const __half* __restrict__ Bm,
    float* __restrict__ C, int N) {
    extern __shared__ __half gsmh[];
    const uint32_t smb = smem_u32(gsmh);

    const int tid  = threadIdx.x;
    const int warp = tid >> 5, lane = tid & 31;
    const int wm = (warp >> 1) * 64;     // 0 or 64
    const int wn = (warp & 1) * 64;      // 0 or 64
    const int frow = lane >> 2;
    const int fcol = lane & 3;

    const __half* Ab = A  + (size_t)blockIdx.y * 128 * Dn;
    const __half* Bb = Bm + (size_t)blockIdx.x * 128 * Dn;

    const int lmat = lane >> 3, lmr = lane & 7;
    uint32_t a_off[4], b_off[4];
    #pragma unroll
    for (int mi = 0; mi < 4; mi++)
        a_off[mi] = (uint32_t)(((wm + mi * 16 + (lmat & 1) * 8 + lmr) * G_HST
                                + (lmat >> 1) * 8) * 2);
    #pragma unroll
    for (int np = 0; np < 4; np++)
        b_off[np] = (uint32_t)(((wn + np * 16 + (lmat >> 1) * 8 + lmr) * G_HST
                                + (lmat & 1) * 8) * 2);

    const int sr  = tid >> 3;            // staging row 0..15
    const int seg = tid & 7;             // 8-half segment

    auto load_chunk = [&](int chunk, int stage) {
        const uint32_t abase = smb + (uint32_t)(stage * G_STAGEH) * 2;
        const uint32_t bbase = abase + G_TILEH * 2;
        const size_t kof = (size_t)chunk * 64 + seg * 8;
        #pragma unroll
        for (int i = 0; i < 8; i++) {
            const int r = sr + i * 16;
            cp_async16(abase + (uint32_t)(r * G_HST + seg * 8) * 2,
                       Ab + (size_t)r * Dn + kof);
            cp_async16(bbase + (uint32_t)(r * G_HST + seg * 8) * 2,
                       Bb + (size_t)r * Dn + kof);
        }
    };

    float acc[4][8][4];
    #pragma unroll
    for (int i = 0; i < 4; i++)
        #pragma unroll
        for (int j = 0; j < 8; j++)
            #pragma unroll
            for (int v = 0; v < 4; v++) acc[i][j][v] = 0.f;

    load_chunk(0, 0); cp_commit();
    load_chunk(1, 1); cp_commit();

    for (int c = 0; c < G_NCH; c++) {
        if (c + 2 < G_NCH) { load_chunk(c + 2, (c + 2) % GS); cp_commit(); }
        const int rem = G_NCH - 1 - c;
        if (rem >= 2)      cp_wait<2>();
        else if (rem == 1) cp_wait<1>();
        else               cp_wait<0>();
        __syncthreads();

        const uint32_t abase = smb + (uint32_t)((c % GS) * G_STAGEH) * 2;
        const uint32_t bbase = abase + G_TILEH * 2;

        #pragma unroll
        for (int kc = 0; kc < 4; kc++) {
            const uint32_t kb = kc * 32;       // 16 halfs = 32 bytes
            uint32_t af[4][4], bf[4][4];
            #pragma unroll
            for (int mi = 0; mi < 4; mi++) ldm4(af[mi], abase + a_off[mi] + kb);
            #pragma unroll
            for (int np = 0; np < 4; np++) ldm4(bf[np], bbase + b_off[np] + kb);
            #pragma unroll
            for (int mi = 0; mi < 4; mi++) {
                #pragma unroll
                for (int nj = 0; nj < 8; nj++) {
                    const uint32_t* b = bf[nj >> 1];
                    if (nj & 1) mma_f16(acc[mi][nj], af[mi], b[2], b[3]);
                    else        mma_f16(acc[mi][nj], af[mi], b[0], b[1]);
                }
            }
        }
        __syncthreads();
    }

    #pragma unroll
    for (int mi = 0; mi < 4; mi++) {
        #pragma unroll
        for (int nj = 0; nj < 8; nj++) {
            const int row = blockIdx.y * 128 + wm + mi * 16 + frow;
            const int col = blockIdx.x * 128 + wn + nj * 8 + fcol * 2;
            *(float2*)(C + (size_t)row * N + col) =
                make_float2(acc[mi][nj][0], acc[mi][nj][1]);
            *(float2*)(C + (size_t)(row + 8) * N + col) =
                make_float2(acc[mi][nj][2], acc[mi][nj][3]);
        }
    }
}

// ---------------------------------------------------------------------------
// 5. Causal flash attention: split-fp16 m16n8k16 mma, V via ldmatrix.trans.
//    LPT scheduling: qt mapped DESCENDING from blockIdx.x so heavy blocks
//    (more KV tiles) launch first, shrinking the final-wave tail.
// ---------------------------------------------------------------------------
#define AST 72
#define ATTN_SMEM ((2*128*AST + 2*64*AST + 2*64*AST + 2*128*AST) * 2)  // 110592

__global__ void __launch_bounds__(256, 2) attn_f16_kernel(
    const float* __restrict__ qkv, float* __restrict__ x) {
    extern __shared__ __half sm[];
    __half* Qhi = sm;
    __half* Qlo = Qhi + 128 * AST;
    __half* Khi = Qlo + 128 * AST;
    __half* Klo = Khi + 64 * AST;
    __half* Vhi = Klo + 64 * AST;     // [token][d], natural layout
    __half* Vlo = Vhi + 64 * AST;
    __half* Phi = Vlo + 64 * AST;
    __half* Plo = Phi + 128 * AST;

    const int qt = gridDim.x - 1 - blockIdx.x;   // heavy (large-qt) blocks first
    const int h  = blockIdx.y;
    const int b  = blockIdx.z;
    const int tid = threadIdx.x;
    const int w = tid >> 5, lane = tid & 31;
    const int gid = lane >> 2, tig = lane & 3;
    const size_t base3 = (size_t)b * Tn * D3;
    const int hoff = h * HDn;

    const int lmat = lane >> 3, lmr = lane & 7;
    const uint32_t qp_off = (uint32_t)(((w * 16 + (lmat & 1) * 8 + lmr) * AST
                                        + (lmat >> 1) * 8) * 2);   // A frags (Q, P)
    uint32_t kv_off[4];   // K: non-trans B frags, storage [n=token][k=d]
    #pragma unroll
    for (int np = 0; np < 4; np++)
        kv_off[np] = (uint32_t)(((np * 16 + (lmat >> 1) * 8 + lmr) * AST
                                 + (lmat & 1) * 8) * 2);
    uint32_t vt_off[4];   // V: TRANS B frags, storage [k=token][n=d]
    #pragma unroll
    for (int np = 0; np < 4; np++)
        vt_off[np] = (uint32_t)((((lmat & 1) * 8 + lmr) * AST
                                 + np * 16 + (lmat >> 1) * 8) * 2);

    const uint32_t qhiA = smem_u32(Qhi), qloA = smem_u32(Qlo);
    const uint32_t khiA = smem_u32(Khi), kloA = smem_u32(Klo);
    const uint32_t vhiA = smem_u32(Vhi), vloA = smem_u32(Vlo);
    const uint32_t phiA = smem_u32(Phi), ploA = smem_u32(Plo);

    // load + split Q tile [128][64]
    #pragma unroll
    for (int it = 0; it < 8; it++) {
        const int i = tid + it * 256;
        const int r = i >> 4, c4 = (i & 15) << 2;
        float4 v = *(const float4*)&qkv[base3 + (size_t)(qt * 128 + r) * D3 + hoff + c4];
        __half2 h01, l01, h23, l23;
        splith2(v.x, v.y, h01, l01);
        splith2(v.z, v.w, h23, l23);
        ((__half2*)Qhi)[r * (AST / 2) + (c4 >> 1)]     = h01;
        ((__half2*)Qhi)[r * (AST / 2) + (c4 >> 1) + 1] = h23;
        ((__half2*)Qlo)[r * (AST / 2) + (c4 >> 1)]     = l01;
        ((__half2*)Qlo)[r * (AST / 2) + (c4 >> 1) + 1] = l23;
    }

    float m0 = -1e30f, m1 = -1e30f, l0 = 0.f, l1 = 0.f;
    float accO[8][4];
    #pragma unroll
    for (int nt = 0; nt < 8; nt++)
        #pragma unroll
        for (int v = 0; v < 4; v++) accO[nt][v] = 0.f;

    const int prow = w * 16 + gid;
    const int r0g = qt * 128 + prow;
    const int r1g = r0g + 8;
    const int jt_end = 2 * qt + 1;

    for (int jt = 0; jt <= jt_end; jt++) {
        __syncthreads();   // prior tile's K/V consumed; Q visible on iter 0
        // load K and V [64][64], both split hi/lo at load (natural layout)
        #pragma unroll
        for (int it = 0; it < 4; it++) {
            const int i = tid + it * 256;
            const int r = i >> 4, c4 = (i & 15) << 2;
            const size_t g = base3 + (size_t)(jt * 64 + r) * D3 + hoff + c4;
            float4 k4 = *(const float4*)&qkv[g + Dn];
            float4 v4 = *(const float4*)&qkv[g + 2 * Dn];
            __half2 h01, l01, h23, l23;
            splith2(k4.x, k4.y, h01, l01);
            splith2(k4.z, k4.w, h23, l23);
            ((__half2*)Khi)[r * (AST / 2) + (c4 >> 1)]     = h01;
            ((__half2*)Khi)[r * (AST / 2) + (c4 >> 1) + 1] = h23;
            ((__half2*)Klo)[r * (AST / 2) + (c4 >> 1)]     = l01;
            ((__half2*)Klo)[r * (AST / 2) + (c4 >> 1) + 1] = l23;
            splith2(v4.x, v4.y, h01, l01);
            splith2(v4.z, v4.w, h23, l23);
            ((__half2*)Vhi)[r * (AST / 2) + (c4 >> 1)]     = h01;
            ((__half2*)Vhi)[r * (AST / 2) + (c4 >> 1) + 1] = h23;
            ((__half2*)Vlo)[r * (AST / 2) + (c4 >> 1)]     = l01;
            ((__half2*)Vlo)[r * (AST / 2) + (c4 >> 1) + 1] = l23;
        }
        __syncthreads();

        // --- S = Q K^T (split-fp16: hh + h.lo + lo.h) ---
        float accS[8][4];
        #pragma unroll
        for (int nt = 0; nt < 8; nt++)
            #pragma unroll
            for (int v = 0; v < 4; v++) accS[nt][v] = 0.f;

        #pragma unroll
        for (int kc = 0; kc < 4; kc++) {
            const uint32_t kb = kc * 32;
            uint32_t ah[4], al[4];
            ldm4(ah, qhiA + qp_off + kb);
            ldm4(al, qloA + qp_off + kb);
            #pragma unroll
            for (int np = 0; np < 4; np++) {
                uint32_t bh[4], bl[4];
                ldm4(bh, khiA + kv_off[np] + kb);
                ldm4(bl, kloA + kv_off[np] + kb);
                mma_f16(accS[2 * np],     ah, bh[0], bh[1]);
                mma_f16(accS[2 * np],     ah, bl[0], bl[1]);
                mma_f16(accS[2 * np],     al, bh[0], bh[1]);
                mma_f16(accS[2 * np + 1], ah, bh[2], bh[3]);
                mma_f16(accS[2 * np + 1], ah, bl[2], bl[3]);
                mma_f16(accS[2 * np + 1], al, bh[2], bh[3]);
            }
        }

        // --- scale + causal mask ---
        const bool diag = (jt * 64 + 63 > qt * 128);
        #pragma unroll
        for (int nt = 0; nt < 8; nt++) {
            const int c0 = jt * 64 + nt * 8 + 2 * tig;
            accS[nt][0] *= 0.125f; accS[nt][1] *= 0.125f;
            accS[nt][2] *= 0.125f; accS[nt][3] *= 0.125f;
            if (diag) {
                if (c0     > r0g) accS[nt][0] = -1e30f;
                if (c0 + 1 > r0g) accS[nt][1] = -1e30f;
                if (c0     > r1g) accS[nt][2] = -1e30f;
                if (c0 + 1 > r1g) accS[nt][3] = -1e30f;
            }
        }

        // --- online softmax ---
        float tm0 = -1e30f, tm1 = -1e30f;
        #pragma unroll
        for (int nt = 0; nt < 8; nt++) {
            tm0 = fmaxf(tm0, fmaxf(accS[nt][0], accS[nt][1]));
            tm1 = fmaxf(tm1, fmaxf(accS[nt][2], accS[nt][3]));
        }
        tm0 = fmaxf(tm0, __shfl_xor_sync(0xffffffffu, tm0, 1));
        tm0 = fmaxf(tm0, __shfl_xor_sync(0xffffffffu, tm0, 2));
        tm1 = fmaxf(tm1, __shfl_xor_sync(0xffffffffu, tm1, 1));
        tm1 = fmaxf(tm1, __shfl_xor_sync(0xffffffffu, tm1, 2));
        const float nm0 = fmaxf(m0, tm0), nm1 = fmaxf(m1, tm1);
        const float corr0 = __expf(m0 - nm0), corr1 = __expf(m1 - nm1);
        m0 = nm0; m1 = nm1;
        float ts0 = 0.f, ts1 = 0.f;
        #pragma unroll
        for (int nt = 0; nt < 8; nt++) {
            accS[nt][0] = __expf(accS[nt][0] - nm0);
            accS[nt][1] = __expf(accS[nt][1] - nm0);
            accS[nt][2] = __expf(accS[nt][2] - nm1);
            accS[nt][3] = __expf(accS[nt][3] - nm1);
            ts0 += accS[nt][0] + accS[nt][1];
            ts1 += accS[nt][2] + accS[nt][3];
        }
        ts0 += __shfl_xor_sync(0xffffffffu, ts0, 1);
        ts0 += __shfl_xor_sync(0xffffffffu, ts0, 2);
        ts1 += __shfl_xor_sync(0xffffffffu, ts1, 1);
        ts1 += __shfl_xor_sync(0xffffffffu, ts1, 2);
        l0 = l0 * corr0 + ts0;
        l1 = l1 * corr1 + ts1;
        #pragma unroll
        for (int nt = 0; nt < 8; nt++) {
            accO[nt][0] *= corr0; accO[nt][1] *= corr0;
            accO[nt][2] *= corr1; accO[nt][3] *= corr1;
        }

        // --- write P (own rows), split fp16 ---
        #pragma unroll
        for (int nt = 0; nt < 8; nt++) {
            __half2 hi2, lo2;
            splith2(accS[nt][0], accS[nt][1], hi2, lo2);
            ((__half2*)Phi)[prow * (AST / 2) + nt * 4 + tig] = hi2;
            ((__half2*)Plo)[prow * (AST / 2) + nt * 4 + tig] = lo2;
            splith2(accS[nt][2], accS[nt][3], hi2, lo2);
            ((__half2*)Phi)[(prow + 8) * (AST / 2) + nt * 4 + tig] = hi2;
            ((__half2*)Plo)[(prow + 8) * (AST / 2) + nt * 4 + tig] = lo2;
        }
        __syncwarp();

        // --- O += P V (split-fp16; V B-frags via ldmatrix.trans) ---
        #pragma unroll
        for (int kc = 0; kc < 4; kc++) {
            const uint32_t kb  = kc * 32;                  // P: 16 halfs along k
            const uint32_t kbv = (uint32_t)(kc * 16 * AST * 2);  // V: 16 token rows
            uint32_t ah[4], al[4];
            ldm4(ah, phiA + qp_off + kb);
            ldm4(al, ploA + qp_off + kb);
            #pragma unroll
            for (int np = 0; np < 4; np++) {
                uint32_t bh[4], bl[4];
                ldm4t(bh, vhiA + vt_off[np] + kbv);
                ldm4t(bl, vloA + vt_off[np] + kbv);
                mma_f16(accO[2 * np],     ah, bh[0], bh[1]);
                mma_f16(accO[2 * np],     ah, bl[0], bl[1]);
                mma_f16(accO[2 * np],     al, bh[0], bh[1]);
                mma_f16(accO[2 * np + 1], ah, bh[2], bh[3]);
                mma_f16(accO[2 * np + 1], ah, bl[2], bl[3]);
                mma_f16(accO[2 * np + 1], al, bh[2], bh[3]);
            }
        }
    }

    // --- epilogue: x += O / l ---
    const float inv0 = 1.0f / l0, inv1 = 1.0f / l1;
    #pragma unroll
    for (int nt = 0; nt < 8; nt++) {
        const int col = hoff + nt * 8 + 2 * tig;
        float* p0 = &x[((size_t)b * Tn + r0g) * Dn + col];
        p0[0] += accO[nt][0] * inv0;
        p0[1] += accO[nt][1] * inv0;
        float* p1 = &x[((size_t)b * Tn + r1g) * Dn + col];
        p1[0] += accO[nt][2] * inv1;
        p1[1] += accO[nt][3] * inv1;
    }
}

// ---------------------------------------------------------------------------
// 6. Per-row NLL (float4 scans)
// ---------------------------------------------------------------------------
__global__ void __launch_bounds__(256) nll_kernel(const float* __restrict__ logits,
                                                  const int* __restrict__ targets,
                                                  float* __restrict__ nll) {
    const int row = blockIdx.x;
    const float* r = logits + (size_t)row * Vn;
    const float4* r4 = (const float4*)r;
    float mx = -3.0e38f;
    for (int v = threadIdx.x; v < Vn / 4; v += 256) {
        float4 q = r4[v];
        mx = fmaxf(mx, fmaxf(fmaxf(q.x, q.y), fmaxf(q.z, q.w)));
    }
    #pragma unroll
    for (int o = 16; o > 0; o >>= 1) mx = fmaxf(mx, __shfl_xor_sync(0xffffffffu, mx, o));
    __shared__ float mb[8];
    __shared__ float sbuf[8];
    const int w = threadIdx.x >> 5, lane = threadIdx.x & 31;
    if (lane == 0) mb[w] = mx;
    __syncthreads();
    float gm = mb[0];
    #pragma unroll
    for (int i = 1; i < 8; i++) gm = fmaxf(gm, mb[i]);

    float se = 0.f;
    for (int v = threadIdx.x; v < Vn / 4; v += 256) {
        float4 q = r4[v];
        se += __expf(q.x - gm) + __expf(q.y - gm) + __expf(q.z - gm) + __expf(q.w - gm);
    }
    #pragma unroll
    for (int o = 16; o > 0; o >>= 1) se += __shfl_xor_sync(0xffffffffu, se, o);
    if (lane == 0) sbuf[w] = se;
    __syncthreads();
    if (threadIdx.x == 0) {
        float tot = 0.f;
        #pragma unroll
        for (int i = 0; i < 8; i++) tot += sbuf[i];
        nll[row] = gm + logf(tot) - r[targets[row]];
    }
}

// ---------------------------------------------------------------------------
// 7. Mean over row NLLs
// ---------------------------------------------------------------------------
__global__ void __launch_bounds__(256) loss_kernel(const float* __restrict__ nll,
                                                   float* __restrict__ out) {
    float s = 0.f;
    for (int i = threadIdx.x; i < BT; i += 256) s += nll[i];
    #pragma unroll
    for (int o = 16; o > 0; o >>= 1) s += __shfl_xor_sync(0xffffffffu, s, o);
    __shared__ float sb[8];
    const int w = threadIdx.x >> 5, lane = threadIdx.x & 31;
    if (lane == 0) sb[w] = s;
    __syncthreads();
    if (threadIdx.x == 0) {
        float tot = 0.f;
        #pragma unroll
        for (int i = 0; i < 8; i++) tot += sb[i];
        out[0] = tot * (1.0f / BT);
    }
}

// ---------------------------------------------------------------------------
// Host entry
// ---------------------------------------------------------------------------
extern "C" void kernel_launch(void* const* d_in, const int* in_sizes, int n_in,
                              void* d_out, int out_size) {
    (void)in_sizes; (void)n_in;
    const float* idx     = (const float*)d_in[0];
    const int*   targets = (const int*)d_in[1];
    const float* W_emb   = (const float*)d_in[2];
    const float* W_attn  = (const float*)d_in[3];
    const float* W_out   = (const float*)d_in[4];
    float* out = (float*)d_out;

    float *x, *qkv, *nll, *lscr, *wembT;
    __half *h, *wattn_h, *wout_h;
    int* tok;
    cudaGetSymbolAddress((void**)&x,       g_x);
    cudaGetSymbolAddress((void**)&h,       g_h);
    cudaGetSymbolAddress((void**)&qkv,     g_qkv);
    cudaGetSymbolAddress((void**)&nll,     g_nll);
    cudaGetSymbolAddress((void**)&lscr,    g_logits_scratch);
    cudaGetSymbolAddress((void**)&wattn_h, g_wattn_h);
    cudaGetSymbolAddress((void**)&wout_h,  g_wout_h);
    cudaGetSymbolAddress((void**)&wembT,   g_wembT);
    cudaGetSymbolAddress((void**)&tok,     g_tok);

    cudaFuncSetAttribute(attn_f16_kernel,
                         cudaFuncAttributeMaxDynamicSharedMemorySize, ATTN_SMEM);
    cudaFuncSetAttribute(gemm_f16_kernel,
                         cudaFuncAttributeMaxDynamicSharedMemorySize, G_SMEM);

    const size_t BTV = (size_t)BT * Vn;
    float* logits = ((size_t)out_size >= BTV) ? out : lscr;
    float* lossp  = ((size_t)out_size > BTV) ? (out + BTV)
                  : ((out_size == 1) ? out : nullptr);

    // prep: fp16 weights + transposed embedding table
    f2h_kernel<<<2048, 256>>>((const float2*)W_attn, (__half2*)wattn_h,
                              (int)((size_t)Ln * D3 * Dn / 2));
    f2h_kernel<<<2048, 256>>>((const float2*)W_out, (__half2*)wout_h,
                              (int)((size_t)Vn * Dn / 2));
    wembT_kernel<<<dim3(Vn / 32, Dn / 32), 256>>>(W_emb, wembT);

    tok_kernel<<<BT, 256>>>(idx, tok);
    embed_kernel<<<BT, 256>>>(wembT, tok, x);

    for (int l = 0; l < Ln; l++) {
        ln_kernel<<<BT, 256>>>(x, h);
        gemm_f16_kernel<<<dim3(D3 / 128, BT / 128), 128, G_SMEM>>>(
            h, wattn_h + (size_t)l * D3 * Dn, qkv, D3);
        attn_f16_kernel<<<dim3(Tn / 128, Hn, Bsz), 256, ATTN_SMEM>>>(qkv, x);
    }

    ln_kernel<<<BT, 256>>>(x, h);
    gemm_f16_kernel<<<dim3(Vn / 128, BT / 128), 128, G_SMEM>>>(h, wout_h, logits, Vn);

    if (lossp) {
        nll_kernel<<<BT, 256>>>(logits, targets, nll);
        loss_kernel<<<1, 256>>>(nll, lossp);
    }
}

// round 14
// speedup vs baseline: 1.0422x; 1.0422x over previous
#include <cuda_runtime.h>
#include <cuda_fp16.h>
#include <cstdint>
#include <cstdio>

// Problem constants
#define Bsz 8
#define Tn  1024
#define Vn  8192
#define Dn  1024
#define Hn  16
#define Ln  6
#define HDn 64
#define BT  (Bsz*Tn)      // 8192 rows
#define D3  (3*Dn)        // 3072

// ---------------------------------------------------------------------------
// Scratch
// ---------------------------------------------------------------------------
__device__ float  g_x[(size_t)BT * Dn];
__device__ __half g_h[(size_t)BT * Dn];              // LN output (fp16)
__device__ float  g_qkv[(size_t)BT * D3];
__device__ float  g_logits_scratch[(size_t)BT * Vn];
__device__ __half g_wattn_h[(size_t)Ln * D3 * Dn];   // fp16 W_attn
__device__ __half g_wout_h[(size_t)Vn * Dn];         // fp16 W_out
__device__ float  g_wembT[(size_t)Vn * Dn];          // W_emb transposed [V,D]
__device__ int    g_tok[BT];
__device__ float  g_nll[BT];

// ---------------------------------------------------------------------------
// helpers
// ---------------------------------------------------------------------------
__device__ __forceinline__ uint32_t smem_u32(const void* p) {
    uint32_t a;
    asm("{ .reg .u64 t; cvta.to.shared.u64 t, %1; cvt.u32.u64 %0, t; }"
        : "=r"(a) : "l"(p));
    return a;
}
__device__ __forceinline__ void cp_async16(uint32_t dst, const void* src) {
    asm volatile("cp.async.cg.shared.global [%0], [%1], 16;" :: "r"(dst), "l"(src));
}
__device__ __forceinline__ void cp_commit() {
    asm volatile("cp.async.commit_group;" ::: "memory");
}
template <int N> __device__ __forceinline__ void cp_wait() {
    asm volatile("cp.async.wait_group %0;" :: "n"(N) : "memory");
}
__device__ __forceinline__ void ldm4(uint32_t* r, uint32_t addr) {
    asm volatile("ldmatrix.sync.aligned.m8n8.x4.shared.b16 {%0,%1,%2,%3}, [%4];"
                 : "=r"(r[0]), "=r"(r[1]), "=r"(r[2]), "=r"(r[3]) : "r"(addr));
}
__device__ __forceinline__ void ldm4t(uint32_t* r, uint32_t addr) {
    asm volatile("ldmatrix.sync.aligned.m8n8.x4.trans.shared.b16 {%0,%1,%2,%3}, [%4];"
                 : "=r"(r[0]), "=r"(r[1]), "=r"(r[2]), "=r"(r[3]) : "r"(addr));
}
__device__ __forceinline__ void mma_f16(float* c, const uint32_t* a,
                                        uint32_t b0, uint32_t b1) {
    asm volatile(
        "mma.sync.aligned.m16n8k16.row.col.f32.f16.f16.f32 "
        "{%0,%1,%2,%3}, {%4,%5,%6,%7}, {%8,%9}, {%0,%1,%2,%3};"
        : "+f"(c[0]), "+f"(c[1]), "+f"(c[2]), "+f"(c[3])
        : "r"(a[0]), "r"(a[1]), "r"(a[2]), "r"(a[3]), "r"(b0), "r"(b1));
}
__device__ __forceinline__ void splith2(float x, float y, __half2& hi, __half2& lo) {
    hi = __floats2half2_rn(x, y);
    float2 b = __half22float2(hi);
    lo = __floats2half2_rn(x - b.x, y - b.y);
}

// ---------------------------------------------------------------------------
// 0a. Convert fp32 weights to fp16 once per launch
// ---------------------------------------------------------------------------
__global__ void __launch_bounds__(256) f2h_kernel(const float2* __restrict__ in,
                                                  __half2* __restrict__ out, int n2) {
    for (int i = blockIdx.x * 256 + threadIdx.x; i < n2; i += gridDim.x * 256) {
        float2 v = in[i];
        out[i] = __floats2half2_rn(v.x, v.y);
    }
}

// ---------------------------------------------------------------------------
// 0b. Transpose W_emb [D,V] -> [V,D] (tiled, conflict-free)
// ---------------------------------------------------------------------------
__global__ void __launch_bounds__(256) wembT_kernel(const float* __restrict__ in,
                                                    float* __restrict__ out) {
    __shared__ float t[32][33];
    const int bv = blockIdx.x * 32, bd = blockIdx.y * 32;
    const int tx = threadIdx.x & 31, ty = threadIdx.x >> 5;   // 32x8
    #pragma unroll
    for (int i = 0; i < 32; i += 8)
        t[ty + i][tx] = in[(size_t)(bd + ty + i) * Vn + bv + tx];
    __syncthreads();
    #pragma unroll
    for (int i = 0; i < 32; i += 8)
        out[(size_t)(bv + ty + i) * Dn + bd + tx] = t[tx][ty + i];
}

// ---------------------------------------------------------------------------
// 1. Token ids from one-hot (float4 scan)
// ---------------------------------------------------------------------------
__global__ void __launch_bounds__(256) tok_kernel(const float* __restrict__ idx,
                                                  int* __restrict__ tok) {
    const int row = blockIdx.x;
    const float4* r = (const float4*)(idx + (size_t)row * Vn);
    for (int v = threadIdx.x; v < Vn / 4; v += 256) {
        float4 q = r[v];
        if (q.x > 0.5f) tok[row] = 4 * v;
        if (q.y > 0.5f) tok[row] = 4 * v + 1;
        if (q.z > 0.5f) tok[row] = 4 * v + 2;
        if (q.w > 0.5f) tok[row] = 4 * v + 3;
    }
}

// ---------------------------------------------------------------------------
// 2. Embedding gather (coalesced via transposed table)
// ---------------------------------------------------------------------------
__global__ void __launch_bounds__(256) embed_kernel(const float* __restrict__ WT,
                                                    const int* __restrict__ tok,
                                                    float* __restrict__ x) {
    const int row = blockIdx.x;
    const int t = tok[row];
    const float4* src = (const float4*)(WT + (size_t)t * Dn);
    float4* dst = (float4*)(x + (size_t)row * Dn);
    dst[threadIdx.x] = src[threadIdx.x];     // 256 threads x float4 = 1024 floats
}

// ---------------------------------------------------------------------------
// 3. LayerNorm -> fp16 output
// ---------------------------------------------------------------------------
__global__ void __launch_bounds__(256) ln_kernel(const float* __restrict__ in,
                                                 __half* __restrict__ out) {
    const int row = blockIdx.x;
    const float* r = in + (size_t)row * Dn;
    float s = 0.f, ss = 0.f;
    for (int d = threadIdx.x; d < Dn; d += 256) {
        float v = r[d];
        s += v; ss += v * v;
    }
    #pragma unroll
    for (int o = 16; o > 0; o >>= 1) {
        s  += __shfl_xor_sync(0xffffffffu, s,  o);
        ss += __shfl_xor_sync(0xffffffffu, ss, o);
    }
    __shared__ float sb[8], qb[8];
    const int w = threadIdx.x >> 5, lane = threadIdx.x & 31;
    if (lane == 0) { sb[w] = s; qb[w] = ss; }
    __syncthreads();
    float ts = 0.f, tq = 0.f;
    #pragma unroll
    for (int i = 0; i < 8; i++) { ts += sb[i]; tq += qb[i]; }
    const float mu   = ts * (1.0f / Dn);
    const float var  = tq * (1.0f / Dn) - mu * mu;
    const float rstd = rsqrtf(var + 1e-5f);
    __half* o2 = out + (size_t)row * Dn;
    for (int d = threadIdx.x; d < Dn; d += 256)
        o2[d] = __float2half_rn((r[d] - mu) * rstd);
}

// ---------------------------------------------------------------------------
// 4. fp16 HMMA GEMM (round-10 config: CTA 128x128, 4 warps, warp tile 64x64,
//    BK=64, 3-stage cp.async, 2 CTAs/SM). C[M,N] = A[M,K]*B[N,K]^T; K=1024.
// ---------------------------------------------------------------------------
#define GS 3
#define G_HST 72
#define G_TILEH (128 * G_HST)
#define G_STAGEH (2 * G_TILEH)
#define G_SMEM (GS * G_STAGEH * 2)      // 110592 bytes
#define G_NCH (Dn / 64)                 // 16

__global__ void __launch_bounds__(128, 2) gemm_f16_kernel(
    const __half* __restrict__ A, const __half* __restrict__ Bm,
    float* __restrict__ C, int N) {
    extern __shared__ __half gsmh[];
    const uint32_t smb = smem_u32(gsmh);

    const int tid  = threadIdx.x;
    const int warp = tid >> 5, lane = tid & 31;
    const int wm = (warp >> 1) * 64;     // 0 or 64
    const int wn = (warp & 1) * 64;      // 0 or 64
    const int frow = lane >> 2;
    const int fcol = lane & 3;

    const __half* Ab = A  + (size_t)blockIdx.y * 128 * Dn;
    const __half* Bb = Bm + (size_t)blockIdx.x * 128 * Dn;

    const int lmat = lane >> 3, lmr = lane & 7;
    uint32_t a_off[4], b_off[4];
    #pragma unroll
    for (int mi = 0; mi < 4; mi++)
        a_off[mi] = (uint32_t)(((wm + mi * 16 + (lmat & 1) * 8 + lmr) * G_HST
                                + (lmat >> 1) * 8) * 2);
    #pragma unroll
    for (int np = 0; np < 4; np++)
        b_off[np] = (uint32_t)(((wn + np * 16 + (lmat >> 1) * 8 + lmr) * G_HST
                                + (lmat & 1) * 8) * 2);

    const int sr  = tid >> 3;            // staging row 0..15
    const int seg = tid & 7;             // 8-half segment

    auto load_chunk = [&](int chunk, int stage) {
        const uint32_t abase = smb + (uint32_t)(stage * G_STAGEH) * 2;
        const uint32_t bbase = abase + G_TILEH * 2;
        const size_t kof = (size_t)chunk * 64 + seg * 8;
        #pragma unroll
        for (int i = 0; i < 8; i++) {
            const int r = sr + i * 16;
            cp_async16(abase + (uint32_t)(r * G_HST + seg * 8) * 2,
                       Ab + (size_t)r * Dn + kof);
            cp_async16(bbase + (uint32_t)(r * G_HST + seg * 8) * 2,
                       Bb + (size_t)r * Dn + kof);
        }
    };

    float acc[4][8][4];
    #pragma unroll
    for (int i = 0; i < 4; i++)
        #pragma unroll
        for (int j = 0; j < 8; j++)
            #pragma unroll
            for (int v = 0; v < 4; v++) acc[i][j][v] = 0.f;

    load_chunk(0, 0); cp_commit();
    load_chunk(1, 1); cp_commit();

    for (int c = 0; c < G_NCH; c++) {
        if (c + 2 < G_NCH) { load_chunk(c + 2, (c + 2) % GS); cp_commit(); }
        const int rem = G_NCH - 1 - c;
        if (rem >= 2)      cp_wait<2>();
        else if (rem == 1) cp_wait<1>();
        else               cp_wait<0>();
        __syncthreads();

        const uint32_t abase = smb + (uint32_t)((c % GS) * G_STAGEH) * 2;
        const uint32_t bbase = abase + G_TILEH * 2;

        #pragma unroll
        for (int kc = 0; kc < 4; kc++) {
            const uint32_t kb = kc * 32;       // 16 halfs = 32 bytes
            uint32_t af[4][4], bf[4][4];
            #pragma unroll
            for (int mi = 0; mi < 4; mi++) ldm4(af[mi], abase + a_off[mi] + kb);
            #pragma unroll
            for (int np = 0; np < 4; np++) ldm4(bf[np], bbase + b_off[np] + kb);
            #pragma unroll
            for (int mi = 0; mi < 4; mi++) {
                #pragma unroll
                for (int nj = 0; nj < 8; nj++) {
                    const uint32_t* b = bf[nj >> 1];
                    if (nj & 1) mma_f16(acc[mi][nj], af[mi], b[2], b[3]);
                    else        mma_f16(acc[mi][nj], af[mi], b[0], b[1]);
                }
            }
        }
        __syncthreads();
    }

    #pragma unroll
    for (int mi = 0; mi < 4; mi++) {
        #pragma unroll
        for (int nj = 0; nj < 8; nj++) {
            const int row = blockIdx.y * 128 + wm + mi * 16 + frow;
            const int col = blockIdx.x * 128 + wn + nj * 8 + fcol * 2;
            *(float2*)(C + (size_t)row * N + col) =
                make_float2(acc[mi][nj][0], acc[mi][nj][1]);
            *(float2*)(C + (size_t)(row + 8) * N + col) =
                make_float2(acc[mi][nj][2], acc[mi][nj][3]);
        }
    }
}

// ---------------------------------------------------------------------------
// 5. Causal flash attention: split-fp16 m16n8k16 mma, V via ldmatrix.trans.
//    Warp early-out on fully-masked diagonal half-tile (jt == 2qt+1, warps
//    covering query rows entirely below the tile's key range skip compute).
// ---------------------------------------------------------------------------
#define AST 72
#define ATTN_SMEM ((2*128*AST + 2*64*AST + 2*64*AST + 2*128*AST) * 2)  // 110592

__global__ void __launch_bounds__(256, 2) attn_f16_kernel(
    const float* __restrict__ qkv, float* __restrict__ x) {
    extern __shared__ __half sm[];
    __half* Qhi = sm;
    __half* Qlo = Qhi + 128 * AST;
    __half* Khi = Qlo + 128 * AST;
    __half* Klo = Khi + 64 * AST;
    __half* Vhi = Klo + 64 * AST;     // [token][d], natural layout
    __half* Vlo = Vhi + 64 * AST;
    __half* Phi = Vlo + 64 * AST;
    __half* Plo = Phi + 128 * AST;

    const int qt = blockIdx.x;           // 0..7
    const int h  = blockIdx.y;
    const int b  = blockIdx.z;
    const int tid = threadIdx.x;
    const int w = tid >> 5, lane = tid & 31;
    const int gid = lane >> 2, tig = lane & 3;
    const size_t base3 = (size_t)b * Tn * D3;
    const int hoff = h * HDn;

    const int lmat = lane >> 3, lmr = lane & 7;
    const uint32_t qp_off = (uint32_t)(((w * 16 + (lmat & 1) * 8 + lmr) * AST
                                        + (lmat >> 1) * 8) * 2);   // A frags (Q, P)
    uint32_t kv_off[4];   // K: non-trans B frags, storage [n=token][k=d]
    #pragma unroll
    for (int np = 0; np < 4; np++)
        kv_off[np] = (uint32_t)(((np * 16 + (lmat >> 1) * 8 + lmr) * AST
                                 + (lmat & 1) * 8) * 2);
    uint32_t vt_off[4];   // V: TRANS B frags, storage [k=token][n=d]
    #pragma unroll
    for (int np = 0; np < 4; np++)
        vt_off[np] = (uint32_t)((((lmat & 1) * 8 + lmr) * AST
                                 + np * 16 + (lmat >> 1) * 8) * 2);

    const uint32_t qhiA = smem_u32(Qhi), qloA = smem_u32(Qlo);
    const uint32_t khiA = smem_u32(Khi), kloA = smem_u32(Klo);
    const uint32_t vhiA = smem_u32(Vhi), vloA = smem_u32(Vlo);
    const uint32_t phiA = smem_u32(Phi), ploA = smem_u32(Plo);

    // load + split Q tile [128][64]
    #pragma unroll
    for (int it = 0; it < 8; it++) {
        const int i = tid + it * 256;
        const int r = i >> 4, c4 = (i & 15) << 2;
        float4 v = *(const float4*)&qkv[base3 + (size_t)(qt * 128 + r) * D3 + hoff + c4];
        __half2 h01, l01, h23, l23;
        splith2(v.x, v.y, h01, l01);
        splith2(v.z, v.w, h23, l23);
        ((__half2*)Qhi)[r * (AST / 2) + (c4 >> 1)]     = h01;
        ((__half2*)Qhi)[r * (AST / 2) + (c4 >> 1) + 1] = h23;
        ((__half2*)Qlo)[r * (AST / 2) + (c4 >> 1)]     = l01;
        ((__half2*)Qlo)[r * (AST / 2) + (c4 >> 1) + 1] = l23;
    }

    float m0 = -1e30f, m1 = -1e30f, l0 = 0.f, l1 = 0.f;
    float accO[8][4];
    #pragma unroll
    for (int nt = 0; nt < 8; nt++)
        #pragma unroll
        for (int v = 0; v < 4; v++) accO[nt][v] = 0.f;

    const int prow = w * 16 + gid;
    const int r0g = qt * 128 + prow;
    const int r1g = r0g + 8;
    const int wmaxrow = qt * 128 + w * 16 + 15;   // warp's highest query row
    const int jt_end = 2 * qt + 1;

    for (int jt = 0; jt <= jt_end; jt++) {
        __syncthreads();   // prior tile's K/V consumed; Q visible on iter 0
        // load K and V [64][64], both split hi/lo at load (natural layout)
        #pragma unroll
        for (int it = 0; it < 4; it++) {
            const int i = tid + it * 256;
            const int r = i >> 4, c4 = (i & 15) << 2;
            const size_t g = base3 + (size_t)(jt * 64 + r) * D3 + hoff + c4;
            float4 k4 = *(const float4*)&qkv[g + Dn];
            float4 v4 = *(const float4*)&qkv[g + 2 * Dn];
            __half2 h01, l01, h23, l23;
            splith2(k4.x, k4.y, h01, l01);
            splith2(k4.z, k4.w, h23, l23);
            ((__half2*)Khi)[r * (AST / 2) + (c4 >> 1)]     = h01;
            ((__half2*)Khi)[r * (AST / 2) + (c4 >> 1) + 1] = h23;
            ((__half2*)Klo)[r * (AST / 2) + (c4 >> 1)]     = l01;
            ((__half2*)Klo)[r * (AST / 2) + (c4 >> 1) + 1] = l23;
            splith2(v4.x, v4.y, h01, l01);
            splith2(v4.z, v4.w, h23, l23);
            ((__half2*)Vhi)[r * (AST / 2) + (c4 >> 1)]     = h01;
            ((__half2*)Vhi)[r * (AST / 2) + (c4 >> 1) + 1] = h23;
            ((__half2*)Vlo)[r * (AST / 2) + (c4 >> 1)]     = l01;
            ((__half2*)Vlo)[r * (AST / 2) + (c4 >> 1) + 1] = l23;
        }
        __syncthreads();

        // warp-uniform early-out: all of this warp's query rows < tile key base
        // => every score is causally masked; skip compute, keep barrier counts.
        if (wmaxrow < jt * 64) continue;

        // --- S = Q K^T (split-fp16: hh + h.lo + lo.h) ---
        float accS[8][4];
        #pragma unroll
        for (int nt = 0; nt < 8; nt++)
            #pragma unroll
            for (int v = 0; v < 4; v++) accS[nt][v] = 0.f;

        #pragma unroll
        for (int kc = 0; kc < 4; kc++) {
            const uint32_t kb = kc * 32;
            uint32_t ah[4], al[4];
            ldm4(ah, qhiA + qp_off + kb);
            ldm4(al, qloA + qp_off + kb);
            #pragma unroll
            for (int np = 0; np < 4; np++) {
                uint32_t bh[4], bl[4];
                ldm4(bh, khiA + kv_off[np] + kb);
                ldm4(bl, kloA + kv_off[np] + kb);
                mma_f16(accS[2 * np],     ah, bh[0], bh[1]);
                mma_f16(accS[2 * np],     ah, bl[0], bl[1]);
                mma_f16(accS[2 * np],     al, bh[0], bh[1]);
                mma_f16(accS[2 * np + 1], ah, bh[2], bh[3]);
                mma_f16(accS[2 * np + 1], ah, bl[2], bl[3]);
                mma_f16(accS[2 * np + 1], al, bh[2], bh[3]);
            }
        }

        // --- scale + causal mask ---
        const bool diag = (jt * 64 + 63 > qt * 128);
        #pragma unroll
        for (int nt = 0; nt < 8; nt++) {
            const int c0 = jt * 64 + nt * 8 + 2 * tig;
            accS[nt][0] *= 0.125f; accS[nt][1] *= 0.125f;
            accS[nt][2] *= 0.125f; accS[nt][3] *= 0.125f;
            if (diag) {
                if (c0     > r0g) accS[nt][0] = -1e30f;
                if (c0 + 1 > r0g) accS[nt][1] = -1e30f;
                if (c0     > r1g) accS[nt][2] = -1e30f;
                if (c0 + 1 > r1g) accS[nt][3] = -1e30f;
            }
        }

        // --- online softmax ---
        float tm0 = -1e30f, tm1 = -1e30f;
        #pragma unroll
        for (int nt = 0; nt < 8; nt++) {
            tm0 = fmaxf(tm0, fmaxf(accS[nt][0], accS[nt][1]));
            tm1 = fmaxf(tm1, fmaxf(accS[nt][2], accS[nt][3]));
        }
        tm0 = fmaxf(tm0, __shfl_xor_sync(0xffffffffu, tm0, 1));
        tm0 = fmaxf(tm0, __shfl_xor_sync(0xffffffffu, tm0, 2));
        tm1 = fmaxf(tm1, __shfl_xor_sync(0xffffffffu, tm1, 1));
        tm1 = fmaxf(tm1, __shfl_xor_sync(0xffffffffu, tm1, 2));
        const float nm0 = fmaxf(m0, tm0), nm1 = fmaxf(m1, tm1);
        const float corr0 = __expf(m0 - nm0), corr1 = __expf(m1 - nm1);
        m0 = nm0; m1 = nm1;
        float ts0 = 0.f, ts1 = 0.f;
        #pragma unroll
        for (int nt = 0; nt < 8; nt++) {
            accS[nt][0] = __expf(accS[nt][0] - nm0);
            accS[nt][1] = __expf(accS[nt][1] - nm0);
            accS[nt][2] = __expf(accS[nt][2] - nm1);
            accS[nt][3] = __expf(accS[nt][3] - nm1);
            ts0 += accS[nt][0] + accS[nt][1];
            ts1 += accS[nt][2] + accS[nt][3];
        }
        ts0 += __shfl_xor_sync(0xffffffffu, ts0, 1);
        ts0 += __shfl_xor_sync(0xffffffffu, ts0, 2);
        ts1 += __shfl_xor_sync(0xffffffffu, ts1, 1);
        ts1 += __shfl_xor_sync(0xffffffffu, ts1, 2);
        l0 = l0 * corr0 + ts0;
        l1 = l1 * corr1 + ts1;
        #pragma unroll
        for (int nt = 0; nt < 8; nt++) {
            accO[nt][0] *= corr0; accO[nt][1] *= corr0;
            accO[nt][2] *= corr1; accO[nt][3] *= corr1;
        }

        // --- write P (own rows), split fp16 ---
        #pragma unroll
        for (int nt = 0; nt < 8; nt++) {
            __half2 hi2, lo2;
            splith2(accS[nt][0], accS[nt][1], hi2, lo2);
            ((__half2*)Phi)[prow * (AST / 2) + nt * 4 + tig] = hi2;
            ((__half2*)Plo)[prow * (AST / 2) + nt * 4 + tig] = lo2;
            splith2(accS[nt][2], accS[nt][3], hi2, lo2);
            ((__half2*)Phi)[(prow + 8) * (AST / 2) + nt * 4 + tig] = hi2;
            ((__half2*)Plo)[(prow + 8) * (AST / 2) + nt * 4 + tig] = lo2;
        }
        __syncwarp();

        // --- O += P V (split-fp16; V B-frags via ldmatrix.trans) ---
        #pragma unroll
        for (int kc = 0; kc < 4; kc++) {
            const uint32_t kb  = kc * 32;                  // P: 16 halfs along k
            const uint32_t kbv = (uint32_t)(kc * 16 * AST * 2);  // V: 16 token rows
            uint32_t ah[4], al[4];
            ldm4(ah, phiA + qp_off + kb);
            ldm4(al, ploA + qp_off + kb);
            #pragma unroll
            for (int np = 0; np < 4; np++) {
                uint32_t bh[4], bl[4];
                ldm4t(bh, vhiA + vt_off[np] + kbv);
                ldm4t(bl, vloA + vt_off[np] + kbv);
                mma_f16(accO[2 * np],     ah, bh[0], bh[1]);
                mma_f16(accO[2 * np],     ah, bl[0], bl[1]);
                mma_f16(accO[2 * np],     al, bh[0], bh[1]);
                mma_f16(accO[2 * np + 1], ah, bh[2], bh[3]);
                mma_f16(accO[2 * np + 1], ah, bl[2], bl[3]);
                mma_f16(accO[2 * np + 1], al, bh[2], bh[3]);
            }
        }
    }

    // --- epilogue: x += O / l ---
    const float inv0 = 1.0f / l0, inv1 = 1.0f / l1;
    #pragma unroll
    for (int nt = 0; nt < 8; nt++) {
        const int col = hoff + nt * 8 + 2 * tig;
        float* p0 = &x[((size_t)b * Tn + r0g) * Dn + col];
        p0[0] += accO[nt][0] * inv0;
        p0[1] += accO[nt][1] * inv0;
        float* p1 = &x[((size_t)b * Tn + r1g) * Dn + col];
        p1[0] += accO[nt][2] * inv1;
        p1[1] += accO[nt][3] * inv1;
    }
}

// ---------------------------------------------------------------------------
// 6. Per-row NLL (float4 scans)
// ---------------------------------------------------------------------------
__global__ void __launch_bounds__(256) nll_kernel(const float* __restrict__ logits,
                                                  const int* __restrict__ targets,
                                                  float* __restrict__ nll) {
    const int row = blockIdx.x;
    const float* r = logits + (size_t)row * Vn;
    const float4* r4 = (const float4*)r;
    float mx = -3.0e38f;
    for (int v = threadIdx.x; v < Vn / 4; v += 256) {
        float4 q = r4[v];
        mx = fmaxf(mx, fmaxf(fmaxf(q.x, q.y), fmaxf(q.z, q.w)));
    }
    #pragma unroll
    for (int o = 16; o > 0; o >>= 1) mx = fmaxf(mx, __shfl_xor_sync(0xffffffffu, mx, o));
    __shared__ float mb[8];
    __shared__ float sbuf[8];
    const int w = threadIdx.x >> 5, lane = threadIdx.x & 31;
    if (lane == 0) mb[w] = mx;
    __syncthreads();
    float gm = mb[0];
    #pragma unroll
    for (int i = 1; i < 8; i++) gm = fmaxf(gm, mb[i]);

    float se = 0.f;
    for (int v = threadIdx.x; v < Vn / 4; v += 256) {
        float4 q = r4[v];
        se += __expf(q.x - gm) + __expf(q.y - gm) + __expf(q.z - gm) + __expf(q.w - gm);
    }
    #pragma unroll
    for (int o = 16; o > 0; o >>= 1) se += __shfl_xor_sync(0xffffffffu, se, o);
    if (lane == 0) sbuf[w] = se;
    __syncthreads();
    if (threadIdx.x == 0) {
        float tot = 0.f;
        #pragma unroll
        for (int i = 0; i < 8; i++) tot += sbuf[i];
        nll[row] = gm + logf(tot) - r[targets[row]];
    }
}

// ---------------------------------------------------------------------------
// 7. Mean over row NLLs
// ---------------------------------------------------------------------------
__global__ void __launch_bounds__(256) loss_kernel(const float* __restrict__ nll,
                                                   float* __restrict__ out) {
    float s = 0.f;
    for (int i = threadIdx.x; i < BT; i += 256) s += nll[i];
    #pragma unroll
    for (int o = 16; o > 0; o >>= 1) s += __shfl_xor_sync(0xffffffffu, s, o);
    __shared__ float sb[8];
    const int w = threadIdx.x >> 5, lane = threadIdx.x & 31;
    if (lane == 0) sb[w] = s;
    __syncthreads();
    if (threadIdx.x == 0) {
        float tot = 0.f;
        #pragma unroll
        for (int i = 0; i < 8; i++) tot += sb[i];
        out[0] = tot * (1.0f / BT);
    }
}

// ---------------------------------------------------------------------------
// Host entry
// ---------------------------------------------------------------------------
extern "C" void kernel_launch(void* const* d_in, const int* in_sizes, int n_in,
                              void* d_out, int out_size) {
    (void)in_sizes; (void)n_in;
    const float* idx     = (const float*)d_in[0];
    const int*   targets = (const int*)d_in[1];
    const float* W_emb   = (const float*)d_in[2];
    const float* W_attn  = (const float*)d_in[3];
    const float* W_out   = (const float*)d_in[4];
    float* out = (float*)d_out;

    float *x, *qkv, *nll, *lscr, *wembT;
    __half *h, *wattn_h, *wout_h;
    int* tok;
    cudaGetSymbolAddress((void**)&x,       g_x);
    cudaGetSymbolAddress((void**)&h,       g_h);
    cudaGetSymbolAddress((void**)&qkv,     g_qkv);
    cudaGetSymbolAddress((void**)&nll,     g_nll);
    cudaGetSymbolAddress((void**)&lscr,    g_logits_scratch);
    cudaGetSymbolAddress((void**)&wattn_h, g_wattn_h);
    cudaGetSymbolAddress((void**)&wout_h,  g_wout_h);
    cudaGetSymbolAddress((void**)&wembT,   g_wembT);
    cudaGetSymbolAddress((void**)&tok,     g_tok);

    cudaFuncSetAttribute(attn_f16_kernel,
                         cudaFuncAttributeMaxDynamicSharedMemorySize, ATTN_SMEM);
    cudaFuncSetAttribute(gemm_f16_kernel,
                         cudaFuncAttributeMaxDynamicSharedMemorySize, G_SMEM);

    const size_t BTV = (size_t)BT * Vn;
    float* logits = ((size_t)out_size >= BTV) ? out : lscr;
    float* lossp  = ((size_t)out_size > BTV) ? (out + BTV)
                  : ((out_size == 1) ? out : nullptr);

    // prep: fp16 weights + transposed embedding table
    f2h_kernel<<<2048, 256>>>((const float2*)W_attn, (__half2*)wattn_h,
                              (int)((size_t)Ln * D3 * Dn / 2));
    f2h_kernel<<<2048, 256>>>((const float2*)W_out, (__half2*)wout_h,
                              (int)((size_t)Vn * Dn / 2));
    wembT_kernel<<<dim3(Vn / 32, Dn / 32), 256>>>(W_emb, wembT);

    tok_kernel<<<BT, 256>>>(idx, tok);
    embed_kernel<<<BT, 256>>>(wembT, tok, x);

    for (int l = 0; l < Ln; l++) {
        ln_kernel<<<BT, 256>>>(x, h);
        gemm_f16_kernel<<<dim3(D3 / 128, BT / 128), 128, G_SMEM>>>(
            h, wattn_h + (size_t)l * D3 * Dn, qkv, D3);
        attn_f16_kernel<<<dim3(Tn / 128, Hn, Bsz), 256, ATTN_SMEM>>>(qkv, x);
    }

    ln_kernel<<<BT, 256>>>(x, h);
    gemm_f16_kernel<<<dim3(Vn / 128, BT / 128), 128, G_SMEM>>>(h, wout_h, logits, Vn);

    if (lossp) {
        nll_kernel<<<BT, 256>>>(logits, targets, nll);
        loss_kernel<<<1, 256>>>(nll, lossp);
    }
}